// round 2
// baseline (speedup 1.0000x reference)
#include <cuda_runtime.h>
#include <cuda_bf16.h>

#define NN 1024
#define HH 96
#define EE 16384

// ---------------- device scratch (no allocation allowed) ----------------
__device__ float g_xA[NN * HH];
__device__ float g_xB[NN * HH];
__device__ float g_m[NN * HH];
__device__ float g_s[NN * HH];
__device__ float g_cnt[NN];
__device__ float g_hi[NN * HH];
__device__ float g_hj[NN * HH];

__device__ __forceinline__ float sigf(float v) {
    return __fdividef(1.0f, 1.0f + __expf(-v));
}
__device__ __forceinline__ float leakyf(float v) {
    return v >= 0.0f ? v : 0.01f * v;
}

// ---------------- K1: x = leaky(x[:, :9] @ W_init.T + b_init); clear cnt ----
__global__ void k_init(const float* __restrict__ x,
                       const float* __restrict__ Wi,
                       const float* __restrict__ bi) {
    int i = blockIdx.x, h = threadIdx.x;
    __shared__ float xs[9];
    if (h < 9) xs[h] = x[i * 10 + h];
    __syncthreads();
    float a = bi[h];
#pragma unroll
    for (int c = 0; c < 9; c++) a = fmaf(xs[c], Wi[h * 9 + c], a);
    g_xA[i * HH + h] = leakyf(a);
    if (h == 0) g_cnt[i] = 0.0f;
}

// ---------------- K2: cnt[t] += 1 per edge (edge_index is int32!) --------
__global__ void k_cnt(const int* __restrict__ ei) {
    int e = blockIdx.x * blockDim.x + threadIdx.x;
    if (e < EE) atomicAdd(&g_cnt[ei[EE + e]], 1.0f);
}

// ---------------- K3: m = x @ W_ggc ; s = 0 ----------------
__global__ void k_mggc(int sel, const float* __restrict__ Wg) {
    const float* xc = sel ? g_xB : g_xA;
    int i = blockIdx.x, h = threadIdx.x;
    __shared__ float xs[HH];
    xs[h] = xc[i * HH + h];
    __syncthreads();
    float a = 0.0f;
#pragma unroll 8
    for (int k = 0; k < HH; k++) a = fmaf(xs[k], Wg[k * HH + h], a);
    g_m[i * HH + h] = a;
    g_s[i * HH + h] = 0.0f;
}

// ---------------- K4: s[tgt] += m[src] ----------------
__global__ void k_scatter(const int* __restrict__ ei) {
    int e = blockIdx.x, h = threadIdx.x;
    int sidx = ei[e];
    int tidx = ei[EE + e];
    atomicAdd(&g_s[tidx * HH + h], g_m[sidx * HH + h]);
}

// ---------------- K5: GRU update (in place on x) ----------------
__global__ void k_gru(int sel,
                      const float* __restrict__ Wih, const float* __restrict__ Whh,
                      const float* __restrict__ bih, const float* __restrict__ bhh) {
    float* xc = sel ? g_xB : g_xA;
    int i = blockIdx.x, h = threadIdx.x;
    __shared__ float ag[HH], xs[HH];
    float c = g_cnt[i];
    c = c > 1.0f ? c : 1.0f;
    ag[h] = __fdividef(g_s[i * HH + h], c);
    xs[h] = xc[i * HH + h];
    __syncthreads();
    float ir = bih[h], iz = bih[HH + h], in = bih[2 * HH + h];
    float hr = bhh[h], hz = bhh[HH + h], hn = bhh[2 * HH + h];
#pragma unroll 4
    for (int k = 0; k < HH; k++) {
        float a = ag[k], xv = xs[k];
        ir = fmaf(a, Wih[h * HH + k], ir);
        iz = fmaf(a, Wih[(HH + h) * HH + k], iz);
        in = fmaf(a, Wih[(2 * HH + h) * HH + k], in);
        hr = fmaf(xv, Whh[h * HH + k], hr);
        hz = fmaf(xv, Whh[(HH + h) * HH + k], hz);
        hn = fmaf(xv, Whh[(2 * HH + h) * HH + k], hn);
    }
    float r = sigf(ir + hr);
    float z = sigf(iz + hz);
    float n = tanhf(in + r * hn);
    xc[i * HH + h] = (1.0f - z) * n + z * xs[h];
}

// ---------------- K6: hi = x@Wa1[:, :H].T + ba1 ; hj = x@Wa1[:, H:].T ----
__global__ void k_proj(int sel, const float* __restrict__ Wa1,
                       const float* __restrict__ ba1) {
    const float* xc = sel ? g_xB : g_xA;
    int i = blockIdx.x, h = threadIdx.x;
    __shared__ float xs[HH];
    xs[h] = xc[i * HH + h];
    __syncthreads();
    float a = ba1[h], b = 0.0f;
#pragma unroll 4
    for (int k = 0; k < HH; k++) {
        a = fmaf(xs[k], Wa1[h * 192 + k], a);
        b = fmaf(xs[k], Wa1[h * 192 + 96 + k], b);
    }
    g_hi[i * HH + h] = a;
    g_hj[i * HH + h] = b;
}

// ---------------- K7: attention coeffs + x = coeffs @ x (fused) ----------
// One block per row i; 8 warps; each warp owns one j at a time.
// adj[i,j]==0 -> whole warp skips the 96-sigmoid dot (≈50% of pairs).
__global__ void __launch_bounds__(256) k_att(int sel,
                                             const int* __restrict__ adj,
                                             const float* __restrict__ Wa2,
                                             const float* __restrict__ ba2) {
    const float* xc = sel ? g_xB : g_xA;
    float* xn = sel ? g_xA : g_xB;
    int i = blockIdx.x;
    int tid = threadIdx.x, lane = tid & 31, w = tid >> 5;
    __shared__ float hib[HH], wa2s[HH], sAcc[8][HH];
    if (tid < HH) {
        hib[tid] = g_hi[i * HH + tid];
        wa2s[tid] = Wa2[tid];
    }
    __syncthreads();
    const float b2 = ba2[0];
    const float h0 = hib[lane], h1 = hib[lane + 32], h2 = hib[lane + 64];
    const float w0 = wa2s[lane], w1 = wa2s[lane + 32], w2 = wa2s[lane + 64];
    float a0 = 0.0f, a1 = 0.0f, a2 = 0.0f;
    const int* adjrow = adj + (long)i * NN;
    for (int j = w; j < NN; j += 8) {
        if (adjrow[j] != 0) {
            const float* hjr = &g_hj[j * HH];
            float p = sigf(h0 + hjr[lane]) * w0
                    + sigf(h1 + hjr[lane + 32]) * w1
                    + sigf(h2 + hjr[lane + 64]) * w2;
#pragma unroll
            for (int o = 16; o > 0; o >>= 1) p += __shfl_xor_sync(0xffffffffu, p, o);
            float c = sigf(p + b2);
            const float* xr = &xc[j * HH];
            a0 = fmaf(c, xr[lane], a0);
            a1 = fmaf(c, xr[lane + 32], a1);
            a2 = fmaf(c, xr[lane + 64], a2);
        }
    }
    sAcc[w][lane] = a0;
    sAcc[w][lane + 32] = a1;
    sAcc[w][lane + 64] = a2;
    __syncthreads();
    if (tid < HH) {
        float s = 0.0f;
#pragma unroll
        for (int q = 0; q < 8; q++) s += sAcc[q][tid];
        xn[i * HH + tid] = s;
    }
}

// ---------------- K8: output head ----------------
__global__ void k_out(int sel,
                      const float* __restrict__ Wo1, const float* __restrict__ bo1,
                      const float* __restrict__ Wo2, const float* __restrict__ bo2,
                      const float* __restrict__ Wp1, const float* __restrict__ bp1,
                      const float* __restrict__ Wp2, const float* __restrict__ bp2,
                      float* __restrict__ out) {
    const float* xc = sel ? g_xB : g_xA;
    int i = blockIdx.x, h = threadIdx.x, lane = h & 31, w = h >> 5;
    __shared__ float xs[HH], y1[HH], y2[HH];
    xs[h] = xc[i * HH + h];
    __syncthreads();
    float a = bo1[h];
#pragma unroll 4
    for (int k = 0; k < HH; k++) a = fmaf(xs[k], Wo1[h * HH + k], a);
    y1[h] = leakyf(a);
    __syncthreads();
    a = bo2[h];
#pragma unroll 4
    for (int k = 0; k < HH; k++) a = fmaf(y1[k], Wo2[h * HH + k], a);
    y2[h] = leakyf(a);
    __syncthreads();
    if (w < 2) {
        const float* Wp = (w == 0) ? Wp1 : Wp2;
        float p = y2[lane] * Wp[lane] + y2[lane + 32] * Wp[lane + 32]
                + y2[lane + 64] * Wp[lane + 64];
#pragma unroll
        for (int o = 16; o > 0; o >>= 1) p += __shfl_xor_sync(0xffffffffu, p, o);
        if (lane == 0) {
            float bp = (w == 0) ? bp1[0] : bp2[0];
            out[w * NN + i] = sigf(p + bp);
        }
    }
}

// ---------------- launch ----------------
extern "C" void kernel_launch(void* const* d_in, const int* in_sizes, int n_in,
                              void* d_out, int out_size) {
    const float* x      = (const float*)d_in[0];
    const int*   ei     = (const int*)d_in[1];   // int32! (JAX x64 disabled)
    const int*   adj    = (const int*)d_in[2];
    const float* W_init = (const float*)d_in[3];
    const float* b_init = (const float*)d_in[4];
    const float* W_ggc  = (const float*)d_in[5];
    const float* W_ih   = (const float*)d_in[6];
    const float* W_hh   = (const float*)d_in[7];
    const float* b_ih   = (const float*)d_in[8];
    const float* b_hh   = (const float*)d_in[9];
    const float* Wa1    = (const float*)d_in[10];
    const float* ba1    = (const float*)d_in[11];
    const float* Wa2    = (const float*)d_in[12];
    const float* ba2    = (const float*)d_in[13];
    const float* Wo1    = (const float*)d_in[14];
    const float* bo1    = (const float*)d_in[15];
    const float* Wo2    = (const float*)d_in[16];
    const float* bo2    = (const float*)d_in[17];
    const float* Wp1    = (const float*)d_in[18];
    const float* bp1    = (const float*)d_in[19];
    const float* Wp2    = (const float*)d_in[20];
    const float* bp2    = (const float*)d_in[21];
    float* out = (float*)d_out;

    k_init<<<NN, HH>>>(x, W_init, b_init);
    k_cnt<<<(EE + 255) / 256, 256>>>(ei);

    for (int t = 0; t < 2; t++) {
        // x lives in A when t==0, in B when t==1 (k_att ping-pongs)
        int sel = t & 1;
        k_mggc<<<NN, HH>>>(sel, W_ggc);
        k_scatter<<<EE, HH>>>(ei);
        k_gru<<<NN, HH>>>(sel, W_ih, W_hh, b_ih, b_hh);
        k_proj<<<NN, HH>>>(sel, Wa1, ba1);
        k_att<<<NN, 256>>>(sel, adj, Wa2, ba2);
    }
    // after 2 unrolls x is back in A (sel=0)
    k_out<<<NN, HH>>>(0, Wo1, bo1, Wo2, bo2, Wp1, bp1, Wp2, bp2, out);
}

// round 4
// speedup vs baseline: 2.7712x; 2.7712x over previous
#include <cuda_runtime.h>
#include <cuda_bf16.h>

#define NN 1024
#define HH 96
#define EE 16384
#define TJ 64
#define BI 4

// ---------------- device scratch (no allocation allowed) ----------------
__device__ float g_xA[NN * HH];
__device__ float g_xB[NN * HH];
__device__ float g_m[NN * HH];
__device__ float g_s[NN * HH];
__device__ float g_cnt[NN];
__device__ float g_hip[NN * HH];   // 0.5*(x@Wa1[:, :H].T + ba1)
__device__ float g_hjp[NN * HH];   // 0.5*(x@Wa1[:, H:].T)
// transposed weights (coalesced loads)
__device__ float g_TWih[HH * 288]; // [k][row]  row = gate*96+h
__device__ float g_TWhh[HH * 288];
__device__ float g_TA[HH * 192];   // [k][0..95]=Wa1[h][k], [k][96..191]=Wa1[h][96+k]
__device__ float g_TO1[HH * HH];
__device__ float g_TO2[HH * HH];

__device__ __forceinline__ float sigf(float v) {
    return __fdividef(1.0f, 1.0f + __expf(-v));
}
__device__ __forceinline__ float leakyf(float v) {
    return v >= 0.0f ? v : 0.01f * v;
}
__device__ __forceinline__ float tanhfast(float v) {
    float y;
    asm("tanh.approx.f32 %0, %1;" : "=f"(y) : "f"(v));
    return y;
}

// ---------------- K0: transpose weights (runs once per launch) ----------
__global__ void k_tw(const float* __restrict__ Wih, const float* __restrict__ Whh,
                     const float* __restrict__ Wa1,
                     const float* __restrict__ Wo1, const float* __restrict__ Wo2) {
    int k = blockIdx.x, t = threadIdx.x;       // t in 0..287
    g_TWih[k * 288 + t] = Wih[t * HH + k];
    g_TWhh[k * 288 + t] = Whh[t * HH + k];
    if (t < 192) {
        g_TA[k * 192 + t] = (t < HH) ? Wa1[t * 192 + k]
                                     : Wa1[(t - HH) * 192 + HH + k];
    }
    if (t < HH) {
        g_TO1[k * HH + t] = Wo1[t * HH + k];
        g_TO2[k * HH + t] = Wo2[t * HH + k];
    }
}

// ---------------- K1: x = leaky(x[:, :9] @ W_init.T + b_init); clear cnt ----
__global__ void k_init(const float* __restrict__ x,
                       const float* __restrict__ Wi,
                       const float* __restrict__ bi) {
    int i = blockIdx.x, h = threadIdx.x;
    __shared__ float xs[9];
    if (h < 9) xs[h] = x[i * 10 + h];
    __syncthreads();
    float a = bi[h];
#pragma unroll
    for (int c = 0; c < 9; c++) a = fmaf(xs[c], Wi[h * 9 + c], a);
    g_xA[i * HH + h] = leakyf(a);
    if (h == 0) g_cnt[i] = 0.0f;
}

// ---------------- K2: cnt[t] += 1 per edge (int32 indices) --------------
__global__ void k_cnt(const int* __restrict__ ei) {
    int e = blockIdx.x * blockDim.x + threadIdx.x;
    if (e < EE) atomicAdd(&g_cnt[ei[EE + e]], 1.0f);
}

// ---------------- K3: m = x @ W_ggc ; s = 0 ----------------
__global__ void k_mggc(int sel, const float* __restrict__ Wg) {
    const float* xc = sel ? g_xB : g_xA;
    int i = blockIdx.x, h = threadIdx.x;
    __shared__ float xs[HH];
    xs[h] = xc[i * HH + h];
    __syncthreads();
    float a = 0.0f;
#pragma unroll 8
    for (int k = 0; k < HH; k++) a = fmaf(xs[k], Wg[k * HH + h], a);
    g_m[i * HH + h] = a;
    g_s[i * HH + h] = 0.0f;
}

// ---------------- K4: s[tgt] += m[src] ----------------
__global__ void k_scatter(const int* __restrict__ ei) {
    int e = blockIdx.x, h = threadIdx.x;
    int sidx = ei[e];
    int tidx = ei[EE + e];
    atomicAdd(&g_s[tidx * HH + h], g_m[sidx * HH + h]);
}

// ---------------- K5: GRU update, 2 rows per block ----------------
__global__ void k_gru(int sel,
                      const float* __restrict__ bih, const float* __restrict__ bhh) {
    float* xc = sel ? g_xB : g_xA;
    int i0 = blockIdx.x * 2, h = threadIdx.x;
    __shared__ float ag[2][HH], xs[2][HH];
#pragma unroll
    for (int r = 0; r < 2; r++) {
        float c = g_cnt[i0 + r];
        c = c > 1.0f ? c : 1.0f;
        ag[r][h] = __fdividef(g_s[(i0 + r) * HH + h], c);
        xs[r][h] = xc[(i0 + r) * HH + h];
    }
    __syncthreads();
    float b_r = bih[h] + bhh[h];
    float b_z = bih[HH + h] + bhh[HH + h];
    float b_in = bih[2 * HH + h];
    float b_hn = bhh[2 * HH + h];
    float racc[2] = {b_r, b_r}, zacc[2] = {b_z, b_z};
    float iacc[2] = {b_in, b_in}, nacc[2] = {b_hn, b_hn};
#pragma unroll 4
    for (int k = 0; k < HH; k++) {
        float wr = g_TWih[k * 288 + h];
        float wz = g_TWih[k * 288 + HH + h];
        float wn = g_TWih[k * 288 + 2 * HH + h];
        float vr = g_TWhh[k * 288 + h];
        float vz = g_TWhh[k * 288 + HH + h];
        float vn = g_TWhh[k * 288 + 2 * HH + h];
#pragma unroll
        for (int r = 0; r < 2; r++) {
            float a = ag[r][k], xv = xs[r][k];
            racc[r] = fmaf(a, wr, fmaf(xv, vr, racc[r]));
            zacc[r] = fmaf(a, wz, fmaf(xv, vz, zacc[r]));
            iacc[r] = fmaf(a, wn, iacc[r]);
            nacc[r] = fmaf(xv, vn, nacc[r]);
        }
    }
#pragma unroll
    for (int r = 0; r < 2; r++) {
        float rr = sigf(racc[r]);
        float zz = sigf(zacc[r]);
        float n = tanhf(iacc[r] + rr * nacc[r]);
        xc[(i0 + r) * HH + h] = (1.0f - zz) * n + zz * xs[r][h];
    }
}

// ---------------- K6: hip = 0.5*(x@Wa1a.T + ba1); hjp = 0.5*(x@Wa1b.T) ---
__global__ void k_proj(int sel, const float* __restrict__ ba1) {
    const float* xc = sel ? g_xB : g_xA;
    int i = blockIdx.x, h = threadIdx.x;
    __shared__ float xs[HH];
    xs[h] = xc[i * HH + h];
    __syncthreads();
    float a = ba1[h], b = 0.0f;
#pragma unroll 4
    for (int k = 0; k < HH; k++) {
        a = fmaf(xs[k], g_TA[k * 192 + h], a);
        b = fmaf(xs[k], g_TA[k * 192 + HH + h], b);
    }
    g_hip[i * HH + h] = 0.5f * a;
    g_hjp[i * HH + h] = 0.5f * b;
}

// ---------------- K7: attention + x = coeffs @ x, tiled, BI rows/block ---
// sigma(v) = 0.5 + 0.5*tanh(v/2); inner arg already halved in k_proj.
// p_ij = base + sum_k w'_k * tanh(hip_k + hjp_k),  base = 0.5*sum(Wa2)+ba2
// coeff = adj ? 0.5 + 0.5*tanh(0.5*p) : 0
__global__ void __launch_bounds__(256) k_att(int sel,
                                             const int* __restrict__ adj,
                                             const float* __restrict__ Wa2,
                                             const float* __restrict__ ba2) {
    const float* xc = sel ? g_xB : g_xA;
    float* xn = sel ? g_xA : g_xB;
    int i0 = blockIdx.x * BI;
    int tid = threadIdx.x, lane = tid & 31, w = tid >> 5;
    __shared__ float hi_s[BI][HH];
    __shared__ float w_s[HH];
    __shared__ float tile[TJ][HH + 1];   // 97-float stride: conflict-free
    __shared__ float c_s[BI][TJ];
    __shared__ float sAcc[8][HH];
    __shared__ float bs_s;

    if (tid < HH) w_s[tid] = 0.5f * Wa2[tid];
    for (int f = tid; f < BI * HH; f += 256) {
        int il = f / HH, k = f - il * HH;
        hi_s[il][k] = g_hip[(i0 + il) * HH + k];
    }
    __syncthreads();
    if (tid == 0) {
        float s = ba2[0];
        for (int k = 0; k < HH; k++) s += w_s[k];
        bs_s = s;
    }
    __syncthreads();

    const int jl = tid >> 2, q = tid & 3;
    float wr[24];
#pragma unroll
    for (int s = 0; s < 24; s++) wr[s] = w_s[q * 24 + s];
    const float base = bs_s;

    float a0 = 0.0f, a1 = 0.0f, a2 = 0.0f;
    const int il2 = w >> 1, seg = w & 1;

    for (int jt = 0; jt < NN; jt += TJ) {
        // stage hj' tile (coalesced)
        for (int f = tid; f < TJ * HH; f += 256) {
            int r = f / HH, k = f - r * HH;
            tile[r][k] = g_hjp[jt * HH + f];
        }
        __syncthreads();
        // phase 1: coeffs for BI rows (4 threads per j, 24 k each)
        float cr[BI];
#pragma unroll
        for (int il = 0; il < BI; il++) {
            float p = 0.0f;
#pragma unroll
            for (int s = 0; s < 24; s++) {
                int k = q * 24 + s;
                p = fmaf(wr[s], tanhfast(hi_s[il][k] + tile[jl][k]), p);
            }
            p += __shfl_xor_sync(0xffffffffu, p, 1);
            p += __shfl_xor_sync(0xffffffffu, p, 2);
            cr[il] = p;
        }
        if (q == 0) {
#pragma unroll
            for (int il = 0; il < BI; il++) {
                int a = adj[(long)(i0 + il) * NN + jt + jl];
                float sv = cr[il] + base;
                c_s[il][jl] = a ? fmaf(0.5f, tanhfast(0.5f * sv), 0.5f) : 0.0f;
            }
        }
        __syncthreads();
        // restage x tile into same buffer
        for (int f = tid; f < TJ * HH; f += 256) {
            int r = f / HH, k = f - r * HH;
            tile[r][k] = xc[jt * HH + f];
        }
        __syncthreads();
        // phase 2: warp (il2, seg) accumulates 32 j's for its row
        const float* crow = c_s[il2] + seg * 32;
#pragma unroll 8
        for (int jj = 0; jj < 32; jj++) {
            float c = crow[jj];
            const float* tr = tile[seg * 32 + jj];
            a0 = fmaf(c, tr[lane], a0);
            a1 = fmaf(c, tr[lane + 32], a1);
            a2 = fmaf(c, tr[lane + 64], a2);
        }
        __syncthreads();
    }
    sAcc[w][lane] = a0;
    sAcc[w][lane + 32] = a1;
    sAcc[w][lane + 64] = a2;
    __syncthreads();
    for (int f = tid; f < BI * HH; f += 256) {
        int il = f / HH, h = f - il * HH;
        xn[(i0 + il) * HH + h] = sAcc[2 * il][h] + sAcc[2 * il + 1][h];
    }
}

// ---------------- K8: output head ----------------
__global__ void k_out(int sel,
                      const float* __restrict__ bo1, const float* __restrict__ bo2,
                      const float* __restrict__ Wp1, const float* __restrict__ bp1,
                      const float* __restrict__ Wp2, const float* __restrict__ bp2,
                      float* __restrict__ out) {
    const float* xc = sel ? g_xB : g_xA;
    int i = blockIdx.x, h = threadIdx.x, lane = h & 31, w = h >> 5;
    __shared__ float xs[HH], y1[HH], y2[HH];
    xs[h] = xc[i * HH + h];
    __syncthreads();
    float a = bo1[h];
#pragma unroll 4
    for (int k = 0; k < HH; k++) a = fmaf(xs[k], g_TO1[k * HH + h], a);
    y1[h] = leakyf(a);
    __syncthreads();
    a = bo2[h];
#pragma unroll 4
    for (int k = 0; k < HH; k++) a = fmaf(y1[k], g_TO2[k * HH + h], a);
    y2[h] = leakyf(a);
    __syncthreads();
    if (w < 2) {
        const float* Wp = (w == 0) ? Wp1 : Wp2;
        float p = y2[lane] * Wp[lane] + y2[lane + 32] * Wp[lane + 32]
                + y2[lane + 64] * Wp[lane + 64];
#pragma unroll
        for (int o = 16; o > 0; o >>= 1) p += __shfl_xor_sync(0xffffffffu, p, o);
        if (lane == 0) {
            float bp = (w == 0) ? bp1[0] : bp2[0];
            out[w * NN + i] = sigf(p + bp);
        }
    }
}

// ---------------- launch ----------------
extern "C" void kernel_launch(void* const* d_in, const int* in_sizes, int n_in,
                              void* d_out, int out_size) {
    const float* x      = (const float*)d_in[0];
    const int*   ei     = (const int*)d_in[1];   // int32 (JAX x64 disabled)
    const int*   adj    = (const int*)d_in[2];
    const float* W_init = (const float*)d_in[3];
    const float* b_init = (const float*)d_in[4];
    const float* W_ggc  = (const float*)d_in[5];
    const float* W_ih   = (const float*)d_in[6];
    const float* W_hh   = (const float*)d_in[7];
    const float* b_ih   = (const float*)d_in[8];
    const float* b_hh   = (const float*)d_in[9];
    const float* Wa1    = (const float*)d_in[10];
    const float* ba1    = (const float*)d_in[11];
    const float* Wa2    = (const float*)d_in[12];
    const float* ba2    = (const float*)d_in[13];
    const float* bo1    = (const float*)d_in[15];
    const float* bo2    = (const float*)d_in[17];
    const float* Wp1    = (const float*)d_in[18];
    const float* bp1    = (const float*)d_in[19];
    const float* Wp2    = (const float*)d_in[20];
    const float* bp2    = (const float*)d_in[21];
    const float* Wo1    = (const float*)d_in[14];
    const float* Wo2    = (const float*)d_in[16];
    float* out = (float*)d_out;

    k_tw<<<HH, 288>>>(W_ih, W_hh, Wa1, Wo1, Wo2);
    k_init<<<NN, HH>>>(x, W_init, b_init);
    k_cnt<<<(EE + 255) / 256, 256>>>(ei);

    for (int t = 0; t < 2; t++) {
        int sel = t & 1;   // x in A when t==0, in B when t==1
        k_mggc<<<NN, HH>>>(sel, W_ggc);
        k_scatter<<<EE, HH>>>(ei);
        k_gru<<<NN / 2, HH>>>(sel, b_ih, b_hh);
        k_proj<<<NN, HH>>>(sel, ba1);
        k_att<<<NN / BI, 256>>>(sel, adj, Wa2, ba2);
    }
    k_out<<<NN, HH>>>(0, bo1, bo2, Wp1, bp1, Wp2, bp2, out);
}

// round 6
// speedup vs baseline: 3.3002x; 1.1909x over previous
#include <cuda_runtime.h>
#include <cuda_bf16.h>

#define NN 1024
#define HH 96
#define EE 16384
#define TJ 64
#define BI 8

// ---------------- device scratch (no allocation allowed) ----------------
__device__ float g_xA[NN * HH];
__device__ float g_xB[NN * HH];
__device__ float g_m[NN * HH];
__device__ float g_hip[NN * HH];   // 0.5*(x@Wa1[:, :H].T + ba1)
__device__ float g_hjp[NN * HH];   // 0.5*(x@Wa1[:, H:].T)
__device__ int   g_deg[NN];
__device__ int   g_off[NN + 1];
__device__ int   g_cur[NN];
__device__ int   g_csr[EE];
// transposed weights (coalesced loads)
__device__ float g_TWih[HH * 288]; // [k][gate*96+h]
__device__ float g_TWhh[HH * 288];
__device__ float g_TA[HH * 192];
__device__ float g_TO1[HH * HH];
__device__ float g_TO2[HH * HH];

__device__ __forceinline__ float sigf(float v) {
    return __fdividef(1.0f, 1.0f + __expf(-v));
}
__device__ __forceinline__ float leakyf(float v) {
    return v >= 0.0f ? v : 0.01f * v;
}
__device__ __forceinline__ float tanhfast(float v) {
    float y;
    asm("tanh.approx.f32 %0, %1;" : "=f"(y) : "f"(v));
    return y;
}

// ---------------- K0: transpose weights ----------------
__global__ void k_tw(const float* __restrict__ Wih, const float* __restrict__ Whh,
                     const float* __restrict__ Wa1,
                     const float* __restrict__ Wo1, const float* __restrict__ Wo2) {
    int k = blockIdx.x, t = threadIdx.x;       // t in 0..287
    g_TWih[k * 288 + t] = Wih[t * HH + k];
    g_TWhh[k * 288 + t] = Whh[t * HH + k];
    if (t < 192) {
        g_TA[k * 192 + t] = (t < HH) ? Wa1[t * 192 + k]
                                     : Wa1[(t - HH) * 192 + HH + k];
    }
    if (t < HH) {
        g_TO1[k * HH + t] = Wo1[t * HH + k];
        g_TO2[k * HH + t] = Wo2[t * HH + k];
    }
}

// ---------------- K1: x = leaky(x[:, :9] @ W_init.T + b_init) -----------
__global__ void k_init(const float* __restrict__ x,
                       const float* __restrict__ Wi,
                       const float* __restrict__ bi) {
    int i = blockIdx.x, h = threadIdx.x;
    __shared__ float xs[9];
    if (h < 9) xs[h] = x[i * 10 + h];
    __syncthreads();
    float a = bi[h];
#pragma unroll
    for (int c = 0; c < 9; c++) a = fmaf(xs[c], Wi[h * 9 + c], a);
    g_xA[i * HH + h] = leakyf(a);
    if (h == 0) g_deg[i] = 0;
}

// ---------------- K2a: degree count ----------------
__global__ void k_deg(const int* __restrict__ ei) {
    int e = blockIdx.x * blockDim.x + threadIdx.x;
    if (e < EE) atomicAdd(&g_deg[ei[EE + e]], 1);
}

// ---------------- K2b: exclusive-offset scan (1 block, 1024 thr) --------
__global__ void k_scan() {
    __shared__ int sc[NN];
    int t = threadIdx.x;
    sc[t] = g_deg[t];
    __syncthreads();
    for (int o = 1; o < NN; o <<= 1) {
        int u = (t >= o) ? sc[t - o] : 0;
        __syncthreads();
        sc[t] += u;
        __syncthreads();
    }
    g_off[t + 1] = sc[t];
    if (t == 0) g_off[0] = 0;
    g_cur[t] = 0;
}

// ---------------- K2c: fill CSR (src list per target) -------------------
__global__ void k_fill(const int* __restrict__ ei) {
    int e = blockIdx.x * blockDim.x + threadIdx.x;
    if (e < EE) {
        int s = ei[e], t = ei[EE + e];
        int p = atomicAdd(&g_cur[t], 1);
        g_csr[g_off[t] + p] = s;
    }
}

// ---------------- K3: m = x @ W_ggc, 4 rows per block -------------------
__global__ void k_mggc(int sel, const float* __restrict__ Wg) {
    const float* xc = sel ? g_xB : g_xA;
    int i0 = blockIdx.x * 4, h = threadIdx.x;
    __shared__ float xs[4][HH];
#pragma unroll
    for (int r = 0; r < 4; r++) xs[r][h] = xc[(i0 + r) * HH + h];
    __syncthreads();
    float a[4] = {0.f, 0.f, 0.f, 0.f};
#pragma unroll 8
    for (int k = 0; k < HH; k++) {
        float wv = Wg[k * HH + h];
#pragma unroll
        for (int r = 0; r < 4; r++) a[r] = fmaf(xs[r][k], wv, a[r]);
    }
#pragma unroll
    for (int r = 0; r < 4; r++) g_m[(i0 + r) * HH + h] = a[r];
}

// ---------------- K5: GRU with fused CSR gather, 4 rows per block -------
__global__ void k_gru(int sel,
                      const float* __restrict__ bih, const float* __restrict__ bhh) {
    float* xc = sel ? g_xB : g_xA;
    int i0 = blockIdx.x * 4, h = threadIdx.x;
    __shared__ float ag[4][HH], xs[4][HH];
#pragma unroll
    for (int r = 0; r < 4; r++) {
        int row = i0 + r;
        int beg = g_off[row], end = g_off[row + 1];
        float s = 0.0f;
        for (int e = beg; e < end; e++) s += g_m[g_csr[e] * HH + h];
        int d = end - beg;
        float c = (float)(d > 1 ? d : 1);
        ag[r][h] = __fdividef(s, c);
        xs[r][h] = xc[row * HH + h];
    }
    __syncthreads();
    float b_r = bih[h] + bhh[h];
    float b_z = bih[HH + h] + bhh[HH + h];
    float b_in = bih[2 * HH + h];
    float b_hn = bhh[2 * HH + h];
    float racc[4] = {b_r, b_r, b_r, b_r}, zacc[4] = {b_z, b_z, b_z, b_z};
    float iacc[4] = {b_in, b_in, b_in, b_in}, nacc[4] = {b_hn, b_hn, b_hn, b_hn};
#pragma unroll 4
    for (int k = 0; k < HH; k++) {
        float wr = g_TWih[k * 288 + h];
        float wz = g_TWih[k * 288 + HH + h];
        float wn = g_TWih[k * 288 + 2 * HH + h];
        float vr = g_TWhh[k * 288 + h];
        float vz = g_TWhh[k * 288 + HH + h];
        float vn = g_TWhh[k * 288 + 2 * HH + h];
#pragma unroll
        for (int r = 0; r < 4; r++) {
            float a = ag[r][k], xv = xs[r][k];
            racc[r] = fmaf(a, wr, fmaf(xv, vr, racc[r]));
            zacc[r] = fmaf(a, wz, fmaf(xv, vz, zacc[r]));
            iacc[r] = fmaf(a, wn, iacc[r]);
            nacc[r] = fmaf(xv, vn, nacc[r]);
        }
    }
#pragma unroll
    for (int r = 0; r < 4; r++) {
        float rr = sigf(racc[r]);
        float zz = sigf(zacc[r]);
        float n = tanhf(iacc[r] + rr * nacc[r]);
        xc[(i0 + r) * HH + h] = (1.0f - zz) * n + zz * xs[r][h];
    }
}

// ---------------- K6: projections, 4 rows/block; zero xn ----------------
__global__ void k_proj(int sel, const float* __restrict__ ba1) {
    const float* xc = sel ? g_xB : g_xA;
    float* xn = sel ? g_xA : g_xB;
    int i0 = blockIdx.x * 4, h = threadIdx.x;
    __shared__ float xs[4][HH];
#pragma unroll
    for (int r = 0; r < 4; r++) xs[r][h] = xc[(i0 + r) * HH + h];
    __syncthreads();
    float bb = ba1[h];
    float a[4] = {bb, bb, bb, bb};
    float b[4] = {0.f, 0.f, 0.f, 0.f};
#pragma unroll 4
    for (int k = 0; k < HH; k++) {
        float wa = g_TA[k * 192 + h];
        float wb = g_TA[k * 192 + HH + h];
#pragma unroll
        for (int r = 0; r < 4; r++) {
            a[r] = fmaf(xs[r][k], wa, a[r]);
            b[r] = fmaf(xs[r][k], wb, b[r]);
        }
    }
#pragma unroll
    for (int r = 0; r < 4; r++) {
        g_hip[(i0 + r) * HH + h] = 0.5f * a[r];
        g_hjp[(i0 + r) * HH + h] = 0.5f * b[r];
        xn[(i0 + r) * HH + h] = 0.0f;   // accumulation target for k_att
    }
}

// ---------------- K7: attention + x = coeffs @ x ------------------------
// sigma(v) = 0.5 + 0.5*tanh(v/2); inner args pre-halved.
// 8 rows per block, j-range split in 2 (grid = 256), atomicAdd combine.
__global__ void __launch_bounds__(256) k_att(int sel,
                                             const int* __restrict__ adj,
                                             const float* __restrict__ Wa2,
                                             const float* __restrict__ ba2) {
    const float* xc = sel ? g_xB : g_xA;
    float* xn = sel ? g_xA : g_xB;
    const int rg = blockIdx.x >> 1;
    const int jbase = (blockIdx.x & 1) * (NN / 2);
    const int i0 = rg * BI;
    int tid = threadIdx.x, lane = tid & 31, w = tid >> 5;
    __shared__ float hi_s[BI][HH];
    __shared__ float w_s[HH];
    __shared__ float tile[TJ][HH + 1];   // stride 97 -> conflict-free
    __shared__ float c_s[BI][TJ];
    __shared__ float bs_s;

    if (tid < HH) w_s[tid] = 0.5f * Wa2[tid];
    for (int f = tid; f < BI * HH; f += 256) {
        int il = f / HH, k = f - il * HH;
        hi_s[il][k] = g_hip[(i0 + il) * HH + k];
    }
    __syncthreads();
    if (tid == 0) {
        float s = ba2[0];
        for (int k = 0; k < HH; k++) s += w_s[k];
        bs_s = s;
    }
    __syncthreads();

    const int jl = tid >> 2, q = tid & 3;  // 64 j-slots x 4 k-quarters
    float wr[24];
#pragma unroll
    for (int s = 0; s < 24; s++) wr[s] = w_s[q * 24 + s];
    const float base = bs_s;

    float a0 = 0.0f, a1 = 0.0f, a2 = 0.0f;

    for (int jt = 0; jt < NN / 2; jt += TJ) {
        // stage hj' tile (coalesced)
        for (int f = tid; f < TJ * HH; f += 256) {
            int r = f / HH, k = f - r * HH;
            tile[r][k] = g_hjp[(jbase + jt) * HH + f];
        }
        __syncthreads();
        // phase 1: p[il] = sum_k w_k tanh(hi+hj); tile value reused 8x
        float p[BI];
#pragma unroll
        for (int il = 0; il < BI; il++) p[il] = 0.0f;
#pragma unroll 4
        for (int s = 0; s < 24; s++) {
            int k = q * 24 + s;
            float tj = tile[jl][k];
            float ws = wr[s];
#pragma unroll
            for (int il = 0; il < BI; il++)
                p[il] = fmaf(ws, tanhfast(hi_s[il][k] + tj), p[il]);
        }
#pragma unroll
        for (int il = 0; il < BI; il++) {
            p[il] += __shfl_xor_sync(0xffffffffu, p[il], 1);
            p[il] += __shfl_xor_sync(0xffffffffu, p[il], 2);
        }
        if (q == 0) {
            int j = jbase + jt + jl;
#pragma unroll
            for (int il = 0; il < BI; il++) {
                int a = adj[(long)(i0 + il) * NN + j];
                float sv = p[il] + base;
                c_s[il][jl] = a ? fmaf(0.5f, tanhfast(0.5f * sv), 0.5f) : 0.0f;
            }
        }
        __syncthreads();
        // restage x tile
        for (int f = tid; f < TJ * HH; f += 256) {
            int r = f / HH, k = f - r * HH;
            tile[r][k] = xc[(jbase + jt) * HH + f];
        }
        __syncthreads();
        // phase 2: warp w accumulates row (i0+w) over 64 j's
        const float* crow = c_s[w];
#pragma unroll 8
        for (int jj = 0; jj < TJ; jj++) {
            float c = crow[jj];
            const float* tr = tile[jj];
            a0 = fmaf(c, tr[lane], a0);
            a1 = fmaf(c, tr[lane + 32], a1);
            a2 = fmaf(c, tr[lane + 64], a2);
        }
        __syncthreads();
    }
    float* dst = &xn[(i0 + w) * HH];
    atomicAdd(&dst[lane], a0);
    atomicAdd(&dst[lane + 32], a1);
    atomicAdd(&dst[lane + 64], a2);
}

// ---------------- K8: output head ----------------
__global__ void k_out(int sel,
                      const float* __restrict__ bo1, const float* __restrict__ bo2,
                      const float* __restrict__ Wp1, const float* __restrict__ bp1,
                      const float* __restrict__ Wp2, const float* __restrict__ bp2,
                      float* __restrict__ out) {
    const float* xc = sel ? g_xB : g_xA;
    int i = blockIdx.x, h = threadIdx.x, lane = h & 31, w = h >> 5;
    __shared__ float xs[HH], y1[HH], y2[HH];
    xs[h] = xc[i * HH + h];
    __syncthreads();
    float a = bo1[h];
#pragma unroll 4
    for (int k = 0; k < HH; k++) a = fmaf(xs[k], g_TO1[k * HH + h], a);
    y1[h] = leakyf(a);
    __syncthreads();
    a = bo2[h];
#pragma unroll 4
    for (int k = 0; k < HH; k++) a = fmaf(y1[k], g_TO2[k * HH + h], a);
    y2[h] = leakyf(a);
    __syncthreads();
    if (w < 2) {
        const float* Wp = (w == 0) ? Wp1 : Wp2;
        float p = y2[lane] * Wp[lane] + y2[lane + 32] * Wp[lane + 32]
                + y2[lane + 64] * Wp[lane + 64];
#pragma unroll
        for (int o = 16; o > 0; o >>= 1) p += __shfl_xor_sync(0xffffffffu, p, o);
        if (lane == 0) {
            float bp = (w == 0) ? bp1[0] : bp2[0];
            out[w * NN + i] = sigf(p + bp);
        }
    }
}

// ---------------- launch ----------------
extern "C" void kernel_launch(void* const* d_in, const int* in_sizes, int n_in,
                              void* d_out, int out_size) {
    const float* x      = (const float*)d_in[0];
    const int*   ei     = (const int*)d_in[1];   // int32 (JAX x64 disabled)
    const int*   adj    = (const int*)d_in[2];
    const float* W_init = (const float*)d_in[3];
    const float* b_init = (const float*)d_in[4];
    const float* W_ggc  = (const float*)d_in[5];
    const float* W_ih   = (const float*)d_in[6];
    const float* W_hh   = (const float*)d_in[7];
    const float* b_ih   = (const float*)d_in[8];
    const float* b_hh   = (const float*)d_in[9];
    const float* Wa1    = (const float*)d_in[10];
    const float* ba1    = (const float*)d_in[11];
    const float* Wa2    = (const float*)d_in[12];
    const float* ba2    = (const float*)d_in[13];
    const float* Wo1    = (const float*)d_in[14];
    const float* bo1    = (const float*)d_in[15];
    const float* Wo2    = (const float*)d_in[16];
    const float* bo2    = (const float*)d_in[17];
    const float* Wp1    = (const float*)d_in[18];
    const float* bp1    = (const float*)d_in[19];
    const float* Wp2    = (const float*)d_in[20];
    const float* bp2    = (const float*)d_in[21];
    float* out = (float*)d_out;

    k_tw<<<HH, 288>>>(W_ih, W_hh, Wa1, Wo1, Wo2);
    k_init<<<NN, HH>>>(x, W_init, b_init);
    k_deg<<<EE / 256, 256>>>(ei);
    k_scan<<<1, NN>>>();
    k_fill<<<EE / 256, 256>>>(ei);

    for (int t = 0; t < 2; t++) {
        int sel = t & 1;   // x in A when t==0, in B when t==1
        k_mggc<<<NN / 4, HH>>>(sel, W_ggc);
        k_gru<<<NN / 4, HH>>>(sel, b_ih, b_hh);
        k_proj<<<NN / 4, HH>>>(sel, ba1);
        k_att<<<NN / BI * 2, 256>>>(sel, adj, Wa2, ba2);
    }
    k_out<<<NN, HH>>>(0, bo1, bo2, Wp1, bp1, Wp2, bp2, out);
}

// round 9
// speedup vs baseline: 3.7123x; 1.1249x over previous
#include <cuda_runtime.h>
#include <cuda_bf16.h>

#define NN 1024
#define HH 96
#define EE 16384
#define TJ 64
#define BI 8

// ---------------- device scratch (no allocation allowed) ----------------
__device__ float g_xA[NN * HH];
__device__ float g_xB[NN * HH];
__device__ float g_m[NN * HH];
__device__ float g_hip[NN * HH];   // 0.5*(x@Wa1[:, :H].T + ba1)
__device__ float g_hjp[NN * HH];   // 0.5*(x@Wa1[:, H:].T)
__device__ int   g_off[NN + 1];
__device__ int   g_csr[EE];
// transposed weights (coalesced loads)
__device__ float g_TWih[HH * 288]; // [k][gate*96+h]
__device__ float g_TWhh[HH * 288];
__device__ float g_TA[HH * 192];
__device__ float g_TO1[HH * HH];
__device__ float g_TO2[HH * HH];

__device__ __forceinline__ float sigf(float v) {
    return __fdividef(1.0f, 1.0f + __expf(-v));
}
__device__ __forceinline__ float leakyf(float v) {
    return v >= 0.0f ? v : 0.01f * v;
}
__device__ __forceinline__ float tanhfast(float v) {
    float y;
    asm("tanh.approx.f32 %0, %1;" : "=f"(y) : "f"(v));
    return y;
}

// ---------------- K0: weight transpose + input projection ---------------
// blocks [0,96): transpose weights (k = blockIdx)
// blocks [96,438): init, 3 rows per block (288 = 3*96 threads)
__global__ void k_setup(const float* __restrict__ x,
                        const float* __restrict__ Wi, const float* __restrict__ bi,
                        const float* __restrict__ Wih, const float* __restrict__ Whh,
                        const float* __restrict__ Wa1,
                        const float* __restrict__ Wo1, const float* __restrict__ Wo2) {
    int b = blockIdx.x, t = threadIdx.x;
    if (b < HH) {
        int k = b;
        g_TWih[k * 288 + t] = Wih[t * HH + k];
        g_TWhh[k * 288 + t] = Whh[t * HH + k];
        if (t < 192)
            g_TA[k * 192 + t] = (t < HH) ? Wa1[t * 192 + k]
                                         : Wa1[(t - HH) * 192 + HH + k];
        if (t < HH) {
            g_TO1[k * HH + t] = Wo1[t * HH + k];
            g_TO2[k * HH + t] = Wo2[t * HH + k];
        }
    } else {
        int rr = t / HH, h = t - rr * HH;
        int i = (b - HH) * 3 + rr;
        if (i < NN) {
            float a = bi[h];
#pragma unroll
            for (int c = 0; c < 9; c++) a = fmaf(x[i * 10 + c], Wi[h * 9 + c], a);
            g_xA[i * HH + h] = leakyf(a);
        }
    }
}

// ---------------- K1: degree count + scan + CSR fill, one block ---------
__global__ void k_scanfill(const int* __restrict__ ei) {
    __shared__ int cnt[NN];
    __shared__ int cur[NN];
    __shared__ int wsum[32];
    int t = threadIdx.x, lane = t & 31, wid = t >> 5;
    cnt[t] = 0;
    __syncthreads();
    for (int e = t; e < EE; e += NN) atomicAdd(&cnt[ei[EE + e]], 1);
    __syncthreads();
    int d = cnt[t], v = d;
#pragma unroll
    for (int o = 1; o < 32; o <<= 1) {
        int u = __shfl_up_sync(0xffffffffu, v, o);
        if (lane >= o) v += u;
    }
    if (lane == 31) wsum[wid] = v;
    __syncthreads();
    if (wid == 0) {
        int s = wsum[lane];
#pragma unroll
        for (int o = 1; o < 32; o <<= 1) {
            int u = __shfl_up_sync(0xffffffffu, s, o);
            if (lane >= o) s += u;
        }
        wsum[lane] = s;
    }
    __syncthreads();
    int incl = v + (wid ? wsum[wid - 1] : 0);
    g_off[t + 1] = incl;
    if (t == 0) g_off[0] = 0;
    cur[t] = incl - d;          // running cursor starts at exclusive offset
    __syncthreads();
    for (int e = t; e < EE; e += NN) {
        int s = ei[e], tg = ei[EE + e];
        int p = atomicAdd(&cur[tg], 1);
        g_csr[p] = s;
    }
}

// ---------------- K2: m = x @ W_ggc, 4 rows per block -------------------
__global__ void k_mggc(int sel, const float* __restrict__ Wg) {
    const float* xc = sel ? g_xB : g_xA;
    int i0 = blockIdx.x * 4, h = threadIdx.x;
    __shared__ float xs[4][HH];
#pragma unroll
    for (int r = 0; r < 4; r++) xs[r][h] = xc[(i0 + r) * HH + h];
    __syncthreads();
    float a[4] = {0.f, 0.f, 0.f, 0.f};
#pragma unroll 8
    for (int k = 0; k < HH; k++) {
        float wv = Wg[k * HH + h];
#pragma unroll
        for (int r = 0; r < 4; r++) a[r] = fmaf(xs[r][k], wv, a[r]);
    }
#pragma unroll
    for (int r = 0; r < 4; r++) g_m[(i0 + r) * HH + h] = a[r];
}

// ---------------- K3: GRU (CSR gather) + projections fused, 4 rows ------
__global__ void k_gruproj(int sel,
                          const float* __restrict__ bih, const float* __restrict__ bhh,
                          const float* __restrict__ ba1) {
    float* xc = sel ? g_xB : g_xA;
    float* xn = sel ? g_xA : g_xB;
    int i0 = blockIdx.x * 4, h = threadIdx.x;
    __shared__ float ag[4][HH], xs[4][HH];
#pragma unroll
    for (int r = 0; r < 4; r++) {
        int row = i0 + r;
        int beg = g_off[row], end = g_off[row + 1];
        float s = 0.0f;
        for (int e = beg; e < end; e++) s += g_m[g_csr[e] * HH + h];
        int d = end - beg;
        ag[r][h] = __fdividef(s, (float)(d > 1 ? d : 1));
        xs[r][h] = xc[row * HH + h];
    }
    __syncthreads();
    float b_r = bih[h] + bhh[h];
    float b_z = bih[HH + h] + bhh[HH + h];
    float b_in = bih[2 * HH + h];
    float b_hn = bhh[2 * HH + h];
    float racc[4] = {b_r, b_r, b_r, b_r}, zacc[4] = {b_z, b_z, b_z, b_z};
    float iacc[4] = {b_in, b_in, b_in, b_in}, nacc[4] = {b_hn, b_hn, b_hn, b_hn};
#pragma unroll 4
    for (int k = 0; k < HH; k++) {
        float wr = g_TWih[k * 288 + h];
        float wz = g_TWih[k * 288 + HH + h];
        float wn = g_TWih[k * 288 + 2 * HH + h];
        float vr = g_TWhh[k * 288 + h];
        float vz = g_TWhh[k * 288 + HH + h];
        float vn = g_TWhh[k * 288 + 2 * HH + h];
#pragma unroll
        for (int r = 0; r < 4; r++) {
            float a = ag[r][k], xv = xs[r][k];
            racc[r] = fmaf(a, wr, fmaf(xv, vr, racc[r]));
            zacc[r] = fmaf(a, wz, fmaf(xv, vz, zacc[r]));
            iacc[r] = fmaf(a, wn, iacc[r]);
            nacc[r] = fmaf(xv, vn, nacc[r]);
        }
    }
    float xnew[4];
#pragma unroll
    for (int r = 0; r < 4; r++) {
        float rr = sigf(racc[r]);
        float zz = sigf(zacc[r]);
        float n = tanhf(iacc[r] + rr * nacc[r]);
        xnew[r] = (1.0f - zz) * n + zz * xs[r][h];
    }
    __syncthreads();
#pragma unroll
    for (int r = 0; r < 4; r++) xs[r][h] = xnew[r];
    __syncthreads();
    // projections on the new x
    float bb = ba1[h];
    float a[4] = {bb, bb, bb, bb};
    float b[4] = {0.f, 0.f, 0.f, 0.f};
#pragma unroll 4
    for (int k = 0; k < HH; k++) {
        float wa = g_TA[k * 192 + h];
        float wb = g_TA[k * 192 + HH + h];
#pragma unroll
        for (int r = 0; r < 4; r++) {
            a[r] = fmaf(xs[r][k], wa, a[r]);
            b[r] = fmaf(xs[r][k], wb, b[r]);
        }
    }
#pragma unroll
    for (int r = 0; r < 4; r++) {
        int row = i0 + r;
        xc[row * HH + h] = xnew[r];
        g_hip[row * HH + h] = 0.5f * a[r];
        g_hjp[row * HH + h] = 0.5f * b[r];
        xn[row * HH + h] = 0.0f;      // accumulation target for k_att
    }
}

// ---------------- K4: attention + x = coeffs @ x ------------------------
// sigma(v) = 0.5 + 0.5*tanh(v/2); inner args pre-halved.
// 8 rows per block, j-range split in 2 (grid = 256). Phase 2: warps split
// the j range; each x-tile value is read ONCE and applied to all 8 rows.
__global__ void __launch_bounds__(256) k_att(int sel,
                                             const int* __restrict__ adj,
                                             const float* __restrict__ Wa2,
                                             const float* __restrict__ ba2) {
    const float* xc = sel ? g_xB : g_xA;
    float* xn = sel ? g_xA : g_xB;
    const int rg = blockIdx.x >> 1;
    const int jbase = (blockIdx.x & 1) * (NN / 2);
    const int i0 = rg * BI;
    int tid = threadIdx.x, lane = tid & 31, w = tid >> 5;
    __shared__ float hi_s[BI][HH];
    __shared__ float w_s[HH];
    __shared__ float tile[TJ][HH + 1];   // stride 97 -> conflict-free
    __shared__ float c2[TJ][BI];
    __shared__ float bs_s;

    if (tid < HH) w_s[tid] = 0.5f * Wa2[tid];
    for (int f = tid; f < BI * HH; f += 256) {
        int il = f / HH, k = f - il * HH;
        hi_s[il][k] = g_hip[(i0 + il) * HH + k];
    }
    __syncthreads();
    if (tid == 0) {
        float s = ba2[0];
        for (int k = 0; k < HH; k++) s += w_s[k];
        bs_s = s;
    }
    __syncthreads();

    const int jl = tid >> 2, q = tid & 3;  // 64 j-slots x 4 k-quarters
    float wr[24];
#pragma unroll
    for (int s = 0; s < 24; s++) wr[s] = w_s[q * 24 + s];
    const float base = bs_s;

    float a0[BI], a1[BI], a2[BI];
#pragma unroll
    for (int il = 0; il < BI; il++) { a0[il] = 0.f; a1[il] = 0.f; a2[il] = 0.f; }

    for (int jt = 0; jt < NN / 2; jt += TJ) {
        // stage hj' tile (coalesced)
        for (int f = tid; f < TJ * HH; f += 256) {
            int r = f / HH, k = f - r * HH;
            tile[r][k] = g_hjp[(jbase + jt) * HH + f];
        }
        __syncthreads();
        // phase 1: p[il] = sum_k w_k tanh(hi+hj); tile value reused 8x
        float p[BI];
#pragma unroll
        for (int il = 0; il < BI; il++) p[il] = 0.0f;
#pragma unroll 4
        for (int s = 0; s < 24; s++) {
            int k = q * 24 + s;
            float tj = tile[jl][k];
            float ws = wr[s];
#pragma unroll
            for (int il = 0; il < BI; il++)
                p[il] = fmaf(ws, tanhfast(hi_s[il][k] + tj), p[il]);
        }
#pragma unroll
        for (int il = 0; il < BI; il++) {
            p[il] += __shfl_xor_sync(0xffffffffu, p[il], 1);
            p[il] += __shfl_xor_sync(0xffffffffu, p[il], 2);
        }
        if (q == 0) {
            int j = jbase + jt + jl;
#pragma unroll
            for (int il = 0; il < BI; il++) {
                int a = adj[(long)(i0 + il) * NN + j];
                float sv = p[il] + base;
                c2[jl][il] = a ? fmaf(0.5f, tanhfast(0.5f * sv), 0.5f) : 0.0f;
            }
        }
        __syncthreads();
        // restage x tile
        for (int f = tid; f < TJ * HH; f += 256) {
            int r = f / HH, k = f - r * HH;
            tile[r][k] = xc[(jbase + jt) * HH + f];
        }
        __syncthreads();
        // phase 2: warp w owns j's [w*8, w*8+8); x read once, 8 rows
#pragma unroll
        for (int u = 0; u < 8; u++) {
            int jj = w * 8 + u;
            float t0 = tile[jj][lane];
            float t1 = tile[jj][lane + 32];
            float t2 = tile[jj][lane + 64];
#pragma unroll
            for (int il = 0; il < BI; il++) {
                float c = c2[jj][il];
                a0[il] = fmaf(c, t0, a0[il]);
                a1[il] = fmaf(c, t1, a1[il]);
                a2[il] = fmaf(c, t2, a2[il]);
            }
        }
        __syncthreads();
    }
    // combine across warps: alias sAcc onto tile (6144 <= 64*97 floats)
    float* sa = &tile[0][0];
#pragma unroll
    for (int il = 0; il < BI; il++) {
        sa[(w * BI + il) * HH + lane] = a0[il];
        sa[(w * BI + il) * HH + lane + 32] = a1[il];
        sa[(w * BI + il) * HH + lane + 64] = a2[il];
    }
    __syncthreads();
    for (int f = tid; f < BI * HH; f += 256) {
        int il = f / HH, h = f - il * HH;
        float s = 0.0f;
#pragma unroll
        for (int ww = 0; ww < 8; ww++) s += sa[(ww * BI + il) * HH + h];
        atomicAdd(&xn[(i0 + il) * HH + h], s);
    }
}

// ---------------- K5: output head, 4 rows per block ---------------------
__global__ void k_out(int sel,
                      const float* __restrict__ bo1, const float* __restrict__ bo2,
                      const float* __restrict__ Wp1, const float* __restrict__ bp1,
                      const float* __restrict__ Wp2, const float* __restrict__ bp2,
                      float* __restrict__ out) {
    const float* xc = sel ? g_xB : g_xA;
    int i0 = blockIdx.x * 4, h = threadIdx.x, lane = h & 31, w = h >> 5;
    __shared__ float xs[4][HH], y1[4][HH], y2[4][HH];
#pragma unroll
    for (int r = 0; r < 4; r++) xs[r][h] = xc[(i0 + r) * HH + h];
    __syncthreads();
    {
        float bb = bo1[h];
        float a[4] = {bb, bb, bb, bb};
#pragma unroll 4
        for (int k = 0; k < HH; k++) {
            float wv = g_TO1[k * HH + h];
#pragma unroll
            for (int r = 0; r < 4; r++) a[r] = fmaf(xs[r][k], wv, a[r]);
        }
#pragma unroll
        for (int r = 0; r < 4; r++) y1[r][h] = leakyf(a[r]);
    }
    __syncthreads();
    {
        float bb = bo2[h];
        float a[4] = {bb, bb, bb, bb};
#pragma unroll 4
        for (int k = 0; k < HH; k++) {
            float wv = g_TO2[k * HH + h];
#pragma unroll
            for (int r = 0; r < 4; r++) a[r] = fmaf(y1[r][k], wv, a[r]);
        }
#pragma unroll
        for (int r = 0; r < 4; r++) y2[r][h] = leakyf(a[r]);
    }
    __syncthreads();
    if (w < 2) {
        const float* Wp = (w == 0) ? Wp1 : Wp2;
        float bp = (w == 0) ? bp1[0] : bp2[0];
#pragma unroll
        for (int r = 0; r < 4; r++) {
            float p = y2[r][lane] * Wp[lane] + y2[r][lane + 32] * Wp[lane + 32]
                    + y2[r][lane + 64] * Wp[lane + 64];
#pragma unroll
            for (int o = 16; o > 0; o >>= 1) p += __shfl_xor_sync(0xffffffffu, p, o);
            if (lane == 0) out[w * NN + i0 + r] = sigf(p + bp);
        }
    }
}

// ---------------- launch ----------------
extern "C" void kernel_launch(void* const* d_in, const int* in_sizes, int n_in,
                              void* d_out, int out_size) {
    const float* x      = (const float*)d_in[0];
    const int*   ei     = (const int*)d_in[1];   // int32 (JAX x64 disabled)
    const int*   adj    = (const int*)d_in[2];
    const float* W_init = (const float*)d_in[3];
    const float* b_init = (const float*)d_in[4];
    const float* W_ggc  = (const float*)d_in[5];
    const float* W_ih   = (const float*)d_in[6];
    const float* W_hh   = (const float*)d_in[7];
    const float* b_ih   = (const float*)d_in[8];
    const float* b_hh   = (const float*)d_in[9];
    const float* Wa1    = (const float*)d_in[10];
    const float* ba1    = (const float*)d_in[11];
    const float* Wa2    = (const float*)d_in[12];
    const float* ba2    = (const float*)d_in[13];
    const float* Wo1    = (const float*)d_in[14];
    const float* bo1    = (const float*)d_in[15];
    const float* Wo2    = (const float*)d_in[16];
    const float* bo2    = (const float*)d_in[17];
    const float* Wp1    = (const float*)d_in[18];
    const float* bp1    = (const float*)d_in[19];
    const float* Wp2    = (const float*)d_in[20];
    const float* bp2    = (const float*)d_in[21];
    float* out = (float*)d_out;

    k_setup<<<96 + 342, 288>>>(x, W_init, b_init, W_ih, W_hh, Wa1, Wo1, Wo2);
    k_scanfill<<<1, NN>>>(ei);

    for (int t = 0; t < 2; t++) {
        int sel = t & 1;   // x in A when t==0, in B when t==1
        k_mggc<<<NN / 4, HH>>>(sel, W_ggc);
        k_gruproj<<<NN / 4, HH>>>(sel, b_ih, b_hh, ba1);
        k_att<<<NN / BI * 2, 256>>>(sel, adj, Wa2, ba2);
    }
    k_out<<<NN / 4, HH>>>(0, bo1, bo2, Wp1, bp1, Wp2, bp2, out);
}